// round 15
// baseline (speedup 1.0000x reference)
#include <cuda_runtime.h>
#include <cuda_bf16.h>

// RelativePositionEncoding (AF3-style), GB300 sm_103a — R11
//
// out[i,j,:] = W_pos[dr] + W_tok[dt] + same_ent*w_ent + W_chain[dk]
// Fusions (proven since R2):
//   F[0..66)  = W_pos[r]  + W_tok[65]   (d_residue branch, !same_cr)
//   F[66..132)= W_pos[32] + W_tok[t]    (d_token branch,    same_cr)
//   C[e*6+k]  = W_chain[k] + e*w_ent
//
// R11 = R8 (persistent 456x512, half-row units, atomic stealing, sequential
// stores, best 175.1us) + double-buffered sIdx:
//   ping-pong index buffers; per iteration: hot-loop(buf cur, unit u) ->
//   stage(unit nu -> buf cur^1) -> ONE barrier. Warps finishing the hot
//   loop early overlap their staging LDG latency with other warps' stores;
//   barriers 2/unit -> 1/unit; the store stream never idles on a cold
//   stage. sU ping-pongs by iteration parity (no tid0 race).

#define N_TOK 1536
#define CZ 128
#define QJ 768                          // j's per unit (half row)
#define N_UNITS (N_TOK * 2)             // 3072
#define N_CTAS 456                      // 152 SMs * 3
#define NTHREADS 512
#define TBL_FLOATS (144 * CZ)
#define SMEM_BYTES (TBL_FLOATS * 4 + 2 * QJ * 2 + 16)   // table + 2 bufs + sU

__device__ int g_ctr;

__global__ void reset_ctr() { g_ctr = 0; }

__device__ __forceinline__ void stage_unit(int u,
                                           unsigned short* __restrict__ buf,
                                           const int* __restrict__ asym,
                                           const int* __restrict__ resi,
                                           const int* __restrict__ enti,
                                           const int* __restrict__ toki,
                                           const int* __restrict__ symi,
                                           int tid)
{
    const int i  = u >> 1;
    const int jb = (u & 1) * QJ;

    const int ai = __ldg(asym + i);
    const int ri = __ldg(resi + i);
    const int ei = __ldg(enti + i);
    const int ti = __ldg(toki + i);
    const int si = __ldg(symi + i);

    #pragma unroll 2
    for (int t = tid; t < QJ; t += NTHREADS) {
        const int j  = jb + t;
        const int aj = __ldg(asym + j);
        const int rj = __ldg(resi + j);
        const int ej = __ldg(enti + j);
        const int tj = __ldg(toki + j);
        const int sj = __ldg(symi + j);

        const bool sc  = (ai == aj);
        const bool scr = sc && (ri == rj);
        int f;
        if (scr)      f = 66 + min(max(ti - tj + 32, 0), 64);
        else if (sc)  f = min(max(ri - rj + 32, 0), 64);
        else          f = 65;
        const bool se = (ei == ej);
        const int  dk = se ? min(max(si - sj + 2, 0), 4) : 5;
        const int  dc = (se ? 6 : 0) + dk;
        buf[t] = (unsigned short)(f | (dc << 8));
    }
}

__global__ __launch_bounds__(NTHREADS, 3)
void relpos_kernel(const int* __restrict__ asym,
                   const int* __restrict__ resi,
                   const int* __restrict__ enti,
                   const int* __restrict__ toki,
                   const int* __restrict__ symi,
                   const float* __restrict__ W,
                   float* __restrict__ out)
{
    extern __shared__ float sW[];                               // [144][128]
    unsigned short* sIdx0 = (unsigned short*)(sW + TBL_FLOATS); // [QJ]
    unsigned short* sIdx1 = sIdx0 + QJ;                         // [QJ]
    int* sU = (int*)(sIdx1 + QJ);                               // [2]

    const int tid = threadIdx.x;

    // ---- One-time table build (per CTA) ----
    // W rows: [0,66)=pos, [66,132)=tok, 132=w_ent, [133,139)=chain
    #pragma unroll 4
    for (int idx = tid; idx < 132 * CZ; idx += NTHREADS) {
        const int row = idx >> 7;
        const int c   = idx & (CZ - 1);
        float v;
        if (row < 66) v = W[row * CZ + c] + W[131 * CZ + c];   // pos[row]+tok[65]
        else          v = W[32  * CZ + c] + W[row * CZ + c];   // pos[32]+tok[row-66]
        sW[idx] = v;
    }
    for (int idx = tid; idx < 12 * CZ; idx += NTHREADS) {
        const int row = idx >> 7;
        const int c   = idx & (CZ - 1);
        const int e   = row / 6;
        const int k   = row % 6;
        float v = W[(133 + k) * CZ + c];
        if (e) v += W[132 * CZ + c];
        sW[132 * CZ + idx] = v;
    }

    // ---- Pipeline prologue: steal two units, stage the first ----
    if (tid == 0) {
        sU[0] = atomicAdd(&g_ctr, 1);
        sU[1] = atomicAdd(&g_ctr, 1);
    }
    __syncthreads();                  // table + sU visible
    int u  = sU[0];
    int nu = sU[1];
    if (u < N_UNITS) stage_unit(u, sIdx0, asym, resi, enti, toki, symi, tid);
    __syncthreads();                  // sIdx0 ready

    const int lane = tid & 31;
    const int warp = tid >> 5;
    const float4* __restrict__ t4 = reinterpret_cast<const float4*>(sW);
    const float4* __restrict__ c4 = t4 + 132 * 32;
    float4* __restrict__ out4 = reinterpret_cast<float4*>(out);

    unsigned short* bufs[2] = { sIdx0, sIdx1 };
    int cur = 0;
    int it  = 0;

    while (u < N_UNITS) {
        const int i  = u >> 1;
        const int jb = (u & 1) * QJ;
        const unsigned short* __restrict__ sIdx = bufs[cur];

        // ---- Hot loop: 16 warps stride j within the unit, unroll x2 ----
        float4* __restrict__ o = out4 + ((size_t)i * N_TOK + jb) * 32 + lane;

        #pragma unroll 2
        for (int j = warp * 2; j < QJ; j += 32) {
            const unsigned p0 = sIdx[j];
            const unsigned p1 = sIdx[j + 1];

            const float4 a0 = t4[(p0 & 0xFFu) * 32 + lane];
            const float4 b0 = c4[(p0 >> 8)    * 32 + lane];
            const float4 a1 = t4[(p1 & 0xFFu) * 32 + lane];
            const float4 b1 = c4[(p1 >> 8)    * 32 + lane];

            float4 r0, r1;
            r0.x = a0.x + b0.x; r0.y = a0.y + b0.y; r0.z = a0.z + b0.z; r0.w = a0.w + b0.w;
            r1.x = a1.x + b1.x; r1.y = a1.y + b1.y; r1.z = a1.z + b1.z; r1.w = a1.w + b1.w;

            __stcs(&o[(size_t)j * 32],       r0);
            __stcs(&o[(size_t)(j + 1) * 32], r1);
        }

        // ---- Stage next unit into the other buffer (overlapped) ----
        if (nu < N_UNITS)
            stage_unit(nu, bufs[cur ^ 1], asym, resi, enti, toki, symi, tid);
        if (tid == 0) sU[it & 1] = atomicAdd(&g_ctr, 1);   // steal unit after next
        __syncthreads();   // staging done; sU slot visible; WAR on bufs[cur] safe

        u  = nu;
        nu = sU[it & 1];
        cur ^= 1;
        it++;
    }
}

extern "C" void kernel_launch(void* const* d_in, const int* in_sizes, int n_in,
                              void* d_out, int out_size)
{
    const int*   asym = (const int*)d_in[0];
    const int*   resi = (const int*)d_in[1];
    const int*   enti = (const int*)d_in[2];
    const int*   toki = (const int*)d_in[3];
    const int*   symi = (const int*)d_in[4];
    const float* W    = (const float*)d_in[5];
    float*       out  = (float*)d_out;

    cudaFuncSetAttribute(relpos_kernel,
                         cudaFuncAttributeMaxDynamicSharedMemorySize, SMEM_BYTES);

    reset_ctr<<<1, 1>>>();
    relpos_kernel<<<N_CTAS, NTHREADS, SMEM_BYTES>>>(asym, resi, enti, toki, symi, W, out);
}

// round 17
// speedup vs baseline: 1.4273x; 1.4273x over previous
#include <cuda_runtime.h>
#include <cuda_bf16.h>

// RelativePositionEncoding (AF3-style), GB300 sm_103a — R12
//
// out[i,j,:] = W_pos[dr] + W_tok[dt] + same_ent*w_ent + W_chain[dk]
// Fusions (proven since R2):
//   F[0..66)  = W_pos[r]  + W_tok[65]   (d_residue branch, !same_cr)
//   F[66..132)= W_pos[32] + W_tok[t]    (d_token branch,    same_cr)
//   C[e*6+k]  = W_chain[k] + e*w_ent
//
// R12 = R11 (persistent 456x512, half-row units, atomic stealing, sequential
// stores, double-buffered sIdx with 1 barrier/unit) with the smem overflow
// fixed: F row index maxes at 130, so F row 131 is dead — C table moves to
// row offset 131, shrinking the table to 143 rows (73216 B). Total smem
// 76304 B -> 3x(76304+1024)=231984 <= 233472 -> 3 CTAs/SM restored (R11's
// 76816 B pushed footprint 48 B over the carveout -> 2 CTAs + 1.5 waves).

#define N_TOK 1536
#define CZ 128
#define QJ 768                          // j's per unit (half row)
#define N_UNITS (N_TOK * 2)             // 3072
#define N_CTAS 456                      // 152 SMs * 3
#define NTHREADS 512
#define C_ROW 131                       // C table row offset (F rows 0..130)
#define TBL_FLOATS (143 * CZ)           // 131 F rows + 12 C rows = 73216 B
#define SMEM_BYTES (TBL_FLOATS * 4 + 2 * QJ * 2 + 16)   // 76304 B

__device__ int g_ctr;

__global__ void reset_ctr() { g_ctr = 0; }

__device__ __forceinline__ void stage_unit(int u,
                                           unsigned short* __restrict__ buf,
                                           const int* __restrict__ asym,
                                           const int* __restrict__ resi,
                                           const int* __restrict__ enti,
                                           const int* __restrict__ toki,
                                           const int* __restrict__ symi,
                                           int tid)
{
    const int i  = u >> 1;
    const int jb = (u & 1) * QJ;

    const int ai = __ldg(asym + i);
    const int ri = __ldg(resi + i);
    const int ei = __ldg(enti + i);
    const int ti = __ldg(toki + i);
    const int si = __ldg(symi + i);

    #pragma unroll 2
    for (int t = tid; t < QJ; t += NTHREADS) {
        const int j  = jb + t;
        const int aj = __ldg(asym + j);
        const int rj = __ldg(resi + j);
        const int ej = __ldg(enti + j);
        const int tj = __ldg(toki + j);
        const int sj = __ldg(symi + j);

        const bool sc  = (ai == aj);
        const bool scr = sc && (ri == rj);
        int f;
        if (scr)      f = 66 + min(max(ti - tj + 32, 0), 64);   // 66..130
        else if (sc)  f = min(max(ri - rj + 32, 0), 64);        // 0..64
        else          f = 65;                                    // diff chain
        const bool se = (ei == ej);
        const int  dk = se ? min(max(si - sj + 2, 0), 4) : 5;
        const int  dc = (se ? 6 : 0) + dk;
        buf[t] = (unsigned short)(f | (dc << 8));
    }
}

__global__ __launch_bounds__(NTHREADS, 3)
void relpos_kernel(const int* __restrict__ asym,
                   const int* __restrict__ resi,
                   const int* __restrict__ enti,
                   const int* __restrict__ toki,
                   const int* __restrict__ symi,
                   const float* __restrict__ W,
                   float* __restrict__ out)
{
    extern __shared__ float sW[];                               // [143][128]
    unsigned short* sIdx0 = (unsigned short*)(sW + TBL_FLOATS); // [QJ]
    unsigned short* sIdx1 = sIdx0 + QJ;                         // [QJ]
    int* sU = (int*)(sIdx1 + QJ);                               // [2]

    const int tid = threadIdx.x;

    // ---- One-time table build (per CTA) ----
    // W rows: [0,66)=pos, [66,132)=tok, 132=w_ent, [133,139)=chain
    // F rows 0..130 only (row 131 of the old layout is never indexed).
    #pragma unroll 4
    for (int idx = tid; idx < C_ROW * CZ; idx += NTHREADS) {
        const int row = idx >> 7;
        const int c   = idx & (CZ - 1);
        float v;
        if (row < 66) v = W[row * CZ + c] + W[131 * CZ + c];   // pos[row]+tok[65]
        else          v = W[32  * CZ + c] + W[row * CZ + c];   // pos[32]+tok[row-66]
        sW[idx] = v;
    }
    for (int idx = tid; idx < 12 * CZ; idx += NTHREADS) {
        const int row = idx >> 7;
        const int c   = idx & (CZ - 1);
        const int e   = row / 6;
        const int k   = row % 6;
        float v = W[(133 + k) * CZ + c];
        if (e) v += W[132 * CZ + c];
        sW[C_ROW * CZ + idx] = v;
    }

    // ---- Pipeline prologue: steal two units, stage the first ----
    if (tid == 0) {
        sU[0] = atomicAdd(&g_ctr, 1);
        sU[1] = atomicAdd(&g_ctr, 1);
    }
    __syncthreads();                  // table + sU visible
    int u  = sU[0];
    int nu = sU[1];
    if (u < N_UNITS) stage_unit(u, sIdx0, asym, resi, enti, toki, symi, tid);
    __syncthreads();                  // sIdx0 ready

    const int lane = tid & 31;
    const int warp = tid >> 5;
    const float4* __restrict__ t4 = reinterpret_cast<const float4*>(sW);
    const float4* __restrict__ c4 = t4 + C_ROW * 32;
    float4* __restrict__ out4 = reinterpret_cast<float4*>(out);

    int cur = 0;
    int it  = 0;

    while (u < N_UNITS) {
        const int i  = u >> 1;
        const int jb = (u & 1) * QJ;
        const unsigned short* __restrict__ sIdx = cur ? sIdx1 : sIdx0;

        // ---- Hot loop: 16 warps stride j within the unit, unroll x2 ----
        float4* __restrict__ o = out4 + ((size_t)i * N_TOK + jb) * 32 + lane;

        #pragma unroll 2
        for (int j = warp * 2; j < QJ; j += 32) {
            const unsigned p0 = sIdx[j];
            const unsigned p1 = sIdx[j + 1];

            const float4 a0 = t4[(p0 & 0xFFu) * 32 + lane];
            const float4 b0 = c4[(p0 >> 8)    * 32 + lane];
            const float4 a1 = t4[(p1 & 0xFFu) * 32 + lane];
            const float4 b1 = c4[(p1 >> 8)    * 32 + lane];

            float4 r0, r1;
            r0.x = a0.x + b0.x; r0.y = a0.y + b0.y; r0.z = a0.z + b0.z; r0.w = a0.w + b0.w;
            r1.x = a1.x + b1.x; r1.y = a1.y + b1.y; r1.z = a1.z + b1.z; r1.w = a1.w + b1.w;

            __stcs(&o[(size_t)j * 32],       r0);
            __stcs(&o[(size_t)(j + 1) * 32], r1);
        }

        // ---- Stage next unit into the other buffer (overlapped) ----
        if (nu < N_UNITS)
            stage_unit(nu, cur ? sIdx0 : sIdx1, asym, resi, enti, toki, symi, tid);
        if (tid == 0) sU[it & 1] = atomicAdd(&g_ctr, 1);   // steal unit after next
        __syncthreads();   // staging done; sU slot visible; WAR on old buf safe

        u  = nu;
        nu = sU[it & 1];
        cur ^= 1;
        it++;
    }
}

extern "C" void kernel_launch(void* const* d_in, const int* in_sizes, int n_in,
                              void* d_out, int out_size)
{
    const int*   asym = (const int*)d_in[0];
    const int*   resi = (const int*)d_in[1];
    const int*   enti = (const int*)d_in[2];
    const int*   toki = (const int*)d_in[3];
    const int*   symi = (const int*)d_in[4];
    const float* W    = (const float*)d_in[5];
    float*       out  = (float*)d_out;

    cudaFuncSetAttribute(relpos_kernel,
                         cudaFuncAttributeMaxDynamicSharedMemorySize, SMEM_BYTES);

    reset_ctr<<<1, 1>>>();
    relpos_kernel<<<N_CTAS, NTHREADS, SMEM_BYTES>>>(asym, resi, enti, toki, symi, W, out);
}